// round 15
// baseline (speedup 1.0000x reference)
#include <cuda_runtime.h>
#include <cuda_bf16.h>
#include <stdint.h>
#include <math.h>

#define BB     8
#define M_TOT  1026
#define CC     384
#define N1     513
#define N1P    514          // padded (even) score row stride
#define HH     6
#define DD     64
#define BHN    (BB*HH)      // 48
#define MROWS  (BB*N1)      // 4104
#define MROWS2 (BB*M_TOT)   // 8208

// ---- scratch (device globals; no cudaMalloc allowed) ----
__device__ int   g_sel;
// pre-split bf16 intermediates (hi/lo): same total bytes as fp32 equivalents
__device__ __nv_bfloat16 g_Qh [MROWS*CC],  g_Ql [MROWS*CC];
__device__ __nv_bfloat16 g_Kh [MROWS*CC],  g_Kl [MROWS*CC];
__device__ __nv_bfloat16 g_V1h[MROWS*CC],  g_V1l[MROWS*CC];
__device__ __nv_bfloat16 g_V2h[MROWS*CC],  g_V2l[MROWS*CC];
__device__ __nv_bfloat16 g_Oh [MROWS2*CC], g_Ol [MROWS2*CC];
__device__ float g_S [(size_t)BHN*N1*N1P];            // raw fp32 scores (~50.6MB)
__device__ __nv_bfloat16 g_Sh[(size_t)BHN*N1*N1P];    // exp'd scores hi
__device__ __nv_bfloat16 g_Sl[(size_t)BHN*N1*N1P];    // exp'd scores lo
__device__ float g_inv[BHN*N1];                       // 1/rowsum

// ------------------------------------------------------------------
// 0) straight-through gumbel selection: argmax(weights + noise)
// ------------------------------------------------------------------
__global__ void select_kernel(const float* __restrict__ w,
                              const float* __restrict__ g) {
    float best = w[0] + g[0];
    int bi = 0;
    #pragma unroll
    for (int i = 1; i < 4; i++) {
        float v = w[i] + g[i];
        if (v > best) { best = v; bi = i; }
    }
    g_sel = bi;
}

// ==================================================================
// bf16 3-pass (hi/lo split) tensor-core GEMM common pieces
//   BM=128 BN=128 BK=32, 256 threads (8 warps = 2m x 4n), warp=64x32
//   KSTU=20 words/row -> conflict-free ldmatrix
//   dynamic smem: 8 arrays of 10240 B = 81920 B (2 CTAs/SM)
// ==================================================================
#define KST  40         // bf16 row stride
#define KSTU 20         // u32 row stride
#define ARR_ELEMS  (128 * KST)          // 5120 bf16 per array
#define BUF_ELEMS  (4 * ARR_ELEMS)      // 20480 bf16 per buffer
#define ARR_BYTES  (ARR_ELEMS * 2)      // 10240
#define BUF_BYTES  (BUF_ELEMS * 2)      // 40960
#define SMEM_TOTAL (2 * BUF_BYTES)      // 81920

extern __shared__ __nv_bfloat16 dynsmem[];

__device__ __forceinline__ void bf16_split2(float2 f, __nv_bfloat162* hi, __nv_bfloat162* lo) {
    __nv_bfloat16 hx = __float2bfloat16(f.x);
    __nv_bfloat16 hy = __float2bfloat16(f.y);
    __nv_bfloat16 lx = __float2bfloat16(f.x - __bfloat162float(hx));
    __nv_bfloat16 ly = __float2bfloat16(f.y - __bfloat162float(hy));
    hi->x = hx; hi->y = hy;
    lo->x = lx; lo->y = ly;
}

__device__ __forceinline__ void mma_bf16(float* d, uint32_t a0, uint32_t a1,
                                         uint32_t a2, uint32_t a3,
                                         uint32_t b0, uint32_t b1) {
    asm volatile(
        "mma.sync.aligned.m16n8k16.row.col.f32.bf16.bf16.f32 "
        "{%0,%1,%2,%3},{%4,%5,%6,%7},{%8,%9},{%0,%1,%2,%3};"
        : "+f"(d[0]), "+f"(d[1]), "+f"(d[2]), "+f"(d[3])
        : "r"(a0), "r"(a1), "r"(a2), "r"(a3), "r"(b0), "r"(b1));
}

__device__ __forceinline__ void ldsm_x4(uint32_t& r0, uint32_t& r1,
                                        uint32_t& r2, uint32_t& r3, uint32_t a) {
    asm volatile("ldmatrix.sync.aligned.m8n8.x4.shared.b16 {%0,%1,%2,%3},[%4];"
                 : "=r"(r0), "=r"(r1), "=r"(r2), "=r"(r3) : "r"(a));
}

#define FRAG_SETUP()                                                   \
    const int warp = tid >> 5, lane = tid & 31;                        \
    const int wm = warp >> 2, wn = warp & 3;                           \
    const int g = lane >> 2, t = lane & 3;                             \
    const int lt = lane >> 3, lr = lane & 7;                           \
    const int aRow = (lt & 1) * 8 + lr;                                \
    const int aKw  = (lt >> 1) * 4;                                    \
    const int bRow = ((lt >> 1) ? 8 : 0) + lr;                         \
    const int bKw  = (lt & 1) * 4;                                     \
    (void)g; (void)t;

// ldmatrix-based inner loop on one 32-k-chunk given array base addrs
#define MMA_TILE_LOOP_LDSM(d, AhB, AlB, BhB, BlB)                                   \
    _Pragma("unroll")                                                               \
    for (int ks = 0; ks < 2; ks++) {                                                \
        const int ko = ks * 8;                                                      \
        uint32_t bh_[4][2], bl_[4][2];                                              \
        _Pragma("unroll")                                                           \
        for (int ntp = 0; ntp < 2; ntp++) {                                         \
            uint32_t off = (uint32_t)(((wn * 32 + ntp * 16 + bRow) * KSTU + ko + bKw) * 4); \
            ldsm_x4(bh_[2*ntp][0], bh_[2*ntp][1], bh_[2*ntp+1][0], bh_[2*ntp+1][1], (BhB) + off); \
            ldsm_x4(bl_[2*ntp][0], bl_[2*ntp][1], bl_[2*ntp+1][0], bl_[2*ntp+1][1], (BlB) + off); \
        }                                                                           \
        _Pragma("unroll")                                                           \
        for (int mt = 0; mt < 4; mt++) {                                            \
            uint32_t off = (uint32_t)(((wm * 64 + mt * 16 + aRow) * KSTU + ko + aKw) * 4);  \
            uint32_t ah0, ah1, ah2, ah3, al0, al1, al2, al3;                        \
            ldsm_x4(ah0, ah1, ah2, ah3, (AhB) + off);                               \
            ldsm_x4(al0, al1, al2, al3, (AlB) + off);                               \
            _Pragma("unroll")                                                       \
            for (int nt = 0; nt < 4; nt++) {                                        \
                mma_bf16(d[mt][nt], ah0, ah1, ah2, ah3, bh_[nt][0], bh_[nt][1]);    \
                mma_bf16(d[mt][nt], ah0, ah1, ah2, ah3, bl_[nt][0], bl_[nt][1]);    \
                mma_bf16(d[mt][nt], al0, al1, al2, al3, bh_[nt][0], bh_[nt][1]);    \
            }                                                                       \
        }                                                                           \
    }

#define ACC_DECL(d)                                                    \
    float d[4][4][4];                                                  \
    _Pragma("unroll")                                                  \
    for (int i = 0; i < 4; i++)                                        \
        _Pragma("unroll")                                              \
        for (int j = 0; j < 4; j++)                                    \
            _Pragma("unroll")                                          \
            for (int r = 0; r < 4; r++) d[i][j][r] = 0.f;

#define ACC_ZERO(d)                                                    \
    _Pragma("unroll")                                                  \
    for (int i = 0; i < 4; i++)                                        \
        _Pragma("unroll")                                              \
        for (int j = 0; j < 4; j++)                                    \
            _Pragma("unroll")                                          \
            for (int r = 0; r < 4; r++) d[i][j][r] = 0.f;

#define BUF_PTRS(buf)                                                  \
    __nv_bfloat16* Ah = dynsmem + (buf) * BUF_ELEMS;                   \
    __nv_bfloat16* Al = Ah + ARR_ELEMS;                                \
    __nv_bfloat16* Bh = Al + ARR_ELEMS;                                \
    __nv_bfloat16* Bl = Bh + ARR_ELEMS;

// ------------------------------------------------------------------
// 1) input projections via bf16 mma: 4 jobs, grid (3, 33, 4)
//    epilogue writes pre-split hi/lo bf16
// ------------------------------------------------------------------
__global__ __launch_bounds__(256, 2)
void proj_kernel(const float* __restrict__ x,
                 const float* Wq1, const float* bq1,
                 const float* Wq2, const float* bq2,
                 const float* Wk1, const float* bk1,
                 const float* Wk2, const float* bk2,
                 const float* Wv1, const float* bv1,
                 const float* Wv2, const float* bv2) {
    const int job = blockIdx.z;
    const int sel = g_sel;
    const float* W; const float* bias; int off;
    __nv_bfloat16 *OUTh, *OUTl;
    if (job == 0) { int qs = sel >> 1; W = qs ? Wq2 : Wq1; bias = qs ? bq2 : bq1; OUTh = g_Qh;  OUTl = g_Ql;  off = qs ? N1 : 0; }
    else if (job == 1) { int ks = sel & 1; W = ks ? Wk2 : Wk1; bias = ks ? bk2 : bk1; OUTh = g_Kh;  OUTl = g_Kl;  off = ks ? N1 : 0; }
    else if (job == 2) { W = Wv1; bias = bv1; OUTh = g_V1h; OUTl = g_V1l; off = 0;  }
    else               { W = Wv2; bias = bv2; OUTh = g_V2h; OUTl = g_V2l; off = N1; }

    const int m0 = blockIdx.y * 128, n0 = blockIdx.x * 128;
    const int tid = threadIdx.x;
    FRAG_SETUP();
    ACC_DECL(d);
    const uint32_t SB = (uint32_t)__cvta_generic_to_shared(dynsmem);

    auto stage = [&](int k0, int buf) {
        BUF_PTRS(buf);
        #pragma unroll
        for (int it = 0; it < 8; it++) {
            int slot = tid + it * 256;
            int ml = slot >> 4, kp = slot & 15;
            int m = m0 + ml;
            float2 f = make_float2(0.f, 0.f);
            if (m < MROWS) {
                int b = m / N1, n = m % N1;
                f = *(const float2*)&x[((size_t)b * M_TOT + n + off) * CC + k0 + 2 * kp];
            }
            __nv_bfloat162 hi, lo;
            bf16_split2(f, &hi, &lo);
            *(__nv_bfloat162*)&Ah[ml * KST + 2 * kp] = hi;
            *(__nv_bfloat162*)&Al[ml * KST + 2 * kp] = lo;
        }
        #pragma unroll
        for (int it = 0; it < 8; it++) {
            int slot = tid + it * 256;
            int nl = slot & 127, kp = slot >> 7;
            float2 f;
            f.x = W[(size_t)(k0 + 2 * kp)     * CC + n0 + nl];
            f.y = W[(size_t)(k0 + 2 * kp + 1) * CC + n0 + nl];
            __nv_bfloat162 hi, lo;
            bf16_split2(f, &hi, &lo);
            *(__nv_bfloat162*)&Bh[nl * KST + 2 * kp] = hi;
            *(__nv_bfloat162*)&Bl[nl * KST + 2 * kp] = lo;
        }
    };

    stage(0, 0);
    __syncthreads();
    const int NK = CC / 32;                          // 12
    for (int kc = 0; kc < NK; kc++) {
        int cur = kc & 1;
        uint32_t base = SB + cur * BUF_BYTES;
        MMA_TILE_LOOP_LDSM(d, base, base + ARR_BYTES, base + 2 * ARR_BYTES, base + 3 * ARR_BYTES)
        if (kc + 1 < NK) stage((kc + 1) * 32, cur ^ 1);
        __syncthreads();
    }

    #pragma unroll
    for (int mt = 0; mt < 4; mt++) {
        #pragma unroll
        for (int nt = 0; nt < 4; nt++) {
            int m = m0 + wm * 64 + mt * 16 + g;
            int c = n0 + wn * 32 + nt * 8 + 2 * t;
            float b0v = bias[c], b1v = bias[c + 1];
            if (m < MROWS) {
                float2 o; o.x = d[mt][nt][0] + b0v; o.y = d[mt][nt][1] + b1v;
                __nv_bfloat162 hi, lo;
                bf16_split2(o, &hi, &lo);
                *(__nv_bfloat162*)&OUTh[(size_t)m * CC + c] = hi;
                *(__nv_bfloat162*)&OUTl[(size_t)m * CC + c] = lo;
            }
            if (m + 8 < MROWS) {
                float2 o; o.x = d[mt][nt][2] + b0v; o.y = d[mt][nt][3] + b1v;
                __nv_bfloat162 hi, lo;
                bf16_split2(o, &hi, &lo);
                *(__nv_bfloat162*)&OUTh[(size_t)(m + 8) * CC + c] = hi;
                *(__nv_bfloat162*)&OUTl[(size_t)(m + 8) * CC + c] = lo;
            }
        }
    }
}

// ------------------------------------------------------------------
// 2) scores via bf16 mma, Q-resident: grid (5, 48)
//    staging = pure u32 copies of pre-split Q/K
// ------------------------------------------------------------------
__global__ __launch_bounds__(256, 2)
void scores_kernel() {
    const int bh = blockIdx.y;
    const int b = bh / HH, hh = bh % HH;
    const int m0 = blockIdx.x * 128;

    const int tid = threadIdx.x;
    FRAG_SETUP();
    ACC_DECL(d);
    const uint32_t SB = (uint32_t)__cvta_generic_to_shared(dynsmem);

    // ---- stage Q strip once (2 chunks), u32 copies ----
    #pragma unroll
    for (int c = 0; c < 2; c++) {
        __nv_bfloat16* Qh = dynsmem + (2 * c)     * ARR_ELEMS;
        __nv_bfloat16* Ql = dynsmem + (2 * c + 1) * ARR_ELEMS;
        #pragma unroll
        for (int it = 0; it < 8; it++) {
            int slot = tid + it * 256;
            int ml = slot >> 4, kp = slot & 15;
            int qi = m0 + ml;
            uint32_t h = 0, l = 0;
            if (qi < N1) {
                size_t base = ((size_t)b * N1 + qi) * CC + hh * DD + c * 32 + 2 * kp;
                h = *(const uint32_t*)&g_Qh[base];
                l = *(const uint32_t*)&g_Ql[base];
            }
            *(uint32_t*)&Qh[ml * KST + 2 * kp] = h;
            *(uint32_t*)&Ql[ml * KST + 2 * kp] = l;
        }
    }

    const float scale = 0.125f;  // 64^-0.5
    const size_t Sbase = (size_t)bh * N1 * N1P;

    for (int nt0 = 0; nt0 < 5; nt0++) {
        const int n0 = nt0 * 128;
        __syncthreads();     // protect K arrays (and Q on first iter)
        #pragma unroll
        for (int c = 0; c < 2; c++) {
            __nv_bfloat16* Kh = dynsmem + (4 + 2 * c) * ARR_ELEMS;
            __nv_bfloat16* Kl = dynsmem + (5 + 2 * c) * ARR_ELEMS;
            #pragma unroll
            for (int it = 0; it < 8; it++) {
                int slot = tid + it * 256;
                int nl = slot >> 4, kp = slot & 15;
                int kj = n0 + nl;
                uint32_t h = 0, l = 0;
                if (kj < N1) {
                    size_t base = ((size_t)b * N1 + kj) * CC + hh * DD + c * 32 + 2 * kp;
                    h = *(const uint32_t*)&g_Kh[base];
                    l = *(const uint32_t*)&g_Kl[base];
                }
                *(uint32_t*)&Kh[nl * KST + 2 * kp] = h;
                *(uint32_t*)&Kl[nl * KST + 2 * kp] = l;
            }
        }
        __syncthreads();

        ACC_ZERO(d);
        #pragma unroll
        for (int c = 0; c < 2; c++) {
            uint32_t qb = SB + (2 * c) * ARR_BYTES;
            uint32_t kb = SB + (4 + 2 * c) * ARR_BYTES;
            MMA_TILE_LOOP_LDSM(d, qb, qb + ARR_BYTES, kb, kb + ARR_BYTES)
        }

        #pragma unroll
        for (int mt = 0; mt < 4; mt++) {
            #pragma unroll
            for (int nt = 0; nt < 4; nt++) {
                int qi = m0 + wm * 64 + mt * 16 + g;
                int kj = n0 + wn * 32 + nt * 8 + 2 * t;      // even
                if (qi < N1 && kj < N1) {
                    float2 o; o.x = d[mt][nt][0] * scale; o.y = d[mt][nt][1] * scale;
                    *(float2*)&g_S[Sbase + (size_t)qi * N1P + kj] = o;
                }
                if (qi + 8 < N1 && kj < N1) {
                    float2 o; o.x = d[mt][nt][2] * scale; o.y = d[mt][nt][3] * scale;
                    *(float2*)&g_S[Sbase + (size_t)(qi + 8) * N1P + kj] = o;
                }
            }
        }
    }
}

// ------------------------------------------------------------------
// 3) softmax: reads fp32 g_S, writes pre-split exp to g_Sh/g_Sl
//    (same total write bytes), pad slots zeroed, 1/sum to g_inv.
// ------------------------------------------------------------------
__global__ __launch_bounds__(128)
void softmax_kernel() {
    const size_t row = blockIdx.x;
    const float* p = g_S + row * N1P;
    __nv_bfloat16* ph = g_Sh + row * N1P;
    __nv_bfloat16* pl = g_Sl + row * N1P;
    const int t = threadIdx.x;
    __shared__ float redm[4];
    __shared__ float reds[4];

    float v[5];
    float m = -1e30f;
    #pragma unroll
    for (int c = 0; c < 5; c++) {
        int j = t + c * 128;
        v[c] = (j < N1) ? p[j] : -1e30f;
        m = fmaxf(m, v[c]);
    }
    #pragma unroll
    for (int o = 16; o > 0; o >>= 1) m = fmaxf(m, __shfl_xor_sync(0xffffffffu, m, o));
    if ((t & 31) == 0) redm[t >> 5] = m;
    __syncthreads();
    m = fmaxf(fmaxf(redm[0], redm[1]), fmaxf(redm[2], redm[3]));

    float s = 0.f;
    #pragma unroll
    for (int c = 0; c < 5; c++) {
        int j = t + c * 128;
        if (j < N1) {
            float e = __expf(v[c] - m);
            __nv_bfloat16 eh = __float2bfloat16(e);
            ph[j] = eh;
            pl[j] = __float2bfloat16(e - __bfloat162float(eh));
            s += e;
        }
    }
    if (t == 0) {
        ph[N1] = __float2bfloat16(0.f);
        pl[N1] = __float2bfloat16(0.f);
    }
    #pragma unroll
    for (int o = 16; o > 0; o >>= 1) s += __shfl_xor_sync(0xffffffffu, s, o);
    if ((t & 31) == 0) reds[t >> 5] = s;
    __syncthreads();
    if (t == 0) g_inv[row] = 1.f / (reds[0] + reds[1] + reds[2] + reds[3]);
}

// ------------------------------------------------------------------
// 4) AV via bf16 mma: O = expS @ [V1|V2], * 1/sum at epilogue
//    grid (5, 48); K-dim 544; A staging = u32 copies of g_Sh/g_Sl,
//    B staging = bf16 copies of pre-split V; epilogue writes g_Oh/g_Ol
// ------------------------------------------------------------------
__global__ __launch_bounds__(256, 2)
void av_kernel() {
    const int bh = blockIdx.y;
    const int b = bh / HH, hh = bh % HH;
    const int m0 = blockIdx.x * 128;

    const int tid = threadIdx.x;
    FRAG_SETUP();
    ACC_DECL(d);
    const uint32_t SB = (uint32_t)__cvta_generic_to_shared(dynsmem);
    const size_t Sbase = (size_t)bh * N1 * N1P;

    auto stage = [&](int k0, int buf) {
        BUF_PTRS(buf);
        #pragma unroll
        for (int it = 0; it < 8; it++) {
            int slot = tid + it * 256;
            int ml = slot >> 4, kp = slot & 15;
            int qi = m0 + ml, ki = k0 + 2 * kp;
            uint32_t h = 0, l = 0;
            if (qi < N1 && ki < N1) {
                size_t base = Sbase + (size_t)qi * N1P + ki;
                h = *(const uint32_t*)&g_Sh[base];
                l = *(const uint32_t*)&g_Sl[base];
            }
            *(uint32_t*)&Ah[ml * KST + 2 * kp] = h;
            *(uint32_t*)&Al[ml * KST + 2 * kp] = l;
        }
        #pragma unroll
        for (int it = 0; it < 8; it++) {
            int slot = tid + it * 256;
            int nl = slot & 127, kp = slot >> 7;
            int ki = k0 + 2 * kp;
            int col = hh * DD + (nl & 63);
            const __nv_bfloat16* Vh = (nl < 64) ? g_V1h : g_V2h;
            const __nv_bfloat16* Vl = (nl < 64) ? g_V1l : g_V2l;
            __nv_bfloat162 h, l;
            h.x = __float2bfloat16(0.f); h.y = h.x;
            l.x = h.x; l.y = h.x;
            if (ki < N1) {
                size_t base = ((size_t)b * N1 + ki) * CC + col;
                h.x = Vh[base]; l.x = Vl[base];
            }
            if (ki + 1 < N1) {
                size_t base = ((size_t)b * N1 + ki + 1) * CC + col;
                h.y = Vh[base]; l.y = Vl[base];
            }
            *(__nv_bfloat162*)&Bh[nl * KST + 2 * kp] = h;
            *(__nv_bfloat162*)&Bl[nl * KST + 2 * kp] = l;
        }
    };

    stage(0, 0);
    __syncthreads();
    const int NK = 17;                               // 544 / 32
    for (int kc = 0; kc < NK; kc++) {
        int cur = kc & 1;
        uint32_t base = SB + cur * BUF_BYTES;
        MMA_TILE_LOOP_LDSM(d, base, base + ARR_BYTES, base + 2 * ARR_BYTES, base + 3 * ARR_BYTES)
        if (kc + 1 < NK) stage((kc + 1) * 32, cur ^ 1);
        __syncthreads();
    }

    #pragma unroll
    for (int mt = 0; mt < 4; mt++) {
        #pragma unroll
        for (int nt = 0; nt < 4; nt++) {
            int qi = m0 + wm * 64 + mt * 16 + g;
            int c = wn * 32 + nt * 8 + 2 * t;                 // 0..126
            int row_off = (c < 64) ? 0 : N1;
            int ci = hh * DD + (c & 63);
            if (qi < N1) {
                float sc = g_inv[bh * N1 + qi];
                float2 o; o.x = d[mt][nt][0] * sc; o.y = d[mt][nt][1] * sc;
                __nv_bfloat162 hi, lo;
                bf16_split2(o, &hi, &lo);
                size_t base = ((size_t)b * M_TOT + row_off + qi) * CC + ci;
                *(__nv_bfloat162*)&g_Oh[base] = hi;
                *(__nv_bfloat162*)&g_Ol[base] = lo;
            }
            if (qi + 8 < N1) {
                float sc = g_inv[bh * N1 + qi + 8];
                float2 o; o.x = d[mt][nt][2] * sc; o.y = d[mt][nt][3] * sc;
                __nv_bfloat162 hi, lo;
                bf16_split2(o, &hi, &lo);
                size_t base = ((size_t)b * M_TOT + row_off + qi + 8) * CC + ci;
                *(__nv_bfloat162*)&g_Oh[base] = hi;
                *(__nv_bfloat162*)&g_Ol[base] = lo;
            }
        }
    }
}

// ------------------------------------------------------------------
// 5) output projection via bf16 mma: grid (3, 65)
//    A staging = u32 copies of pre-split g_O
// ------------------------------------------------------------------
__global__ __launch_bounds__(256, 2)
void final_kernel(const float* __restrict__ Wo,
                  const float* __restrict__ bo,
                  float* __restrict__ out) {
    const int m0 = blockIdx.y * 128, n0 = blockIdx.x * 128;
    const int tid = threadIdx.x;
    FRAG_SETUP();
    ACC_DECL(d);
    const uint32_t SB = (uint32_t)__cvta_generic_to_shared(dynsmem);

    auto stage = [&](int k0, int buf) {
        BUF_PTRS(buf);
        #pragma unroll
        for (int it = 0; it < 8; it++) {
            int slot = tid + it * 256;
            int ml = slot >> 4, kp = slot & 15;
            int m = m0 + ml;
            uint32_t h = 0, l = 0;
            if (m < MROWS2) {
                size_t base = (size_t)m * CC + k0 + 2 * kp;
                h = *(const uint32_t*)&g_Oh[base];
                l = *(const uint32_t*)&g_Ol[base];
            }
            *(uint32_t*)&Ah[ml * KST + 2 * kp] = h;
            *(uint32_t*)&Al[ml * KST + 2 * kp] = l;
        }
        #pragma unroll
        for (int it = 0; it < 8; it++) {
            int slot = tid + it * 256;
            int nl = slot & 127, kp = slot >> 7;
            float2 f;
            f.x = Wo[(size_t)(k0 + 2 * kp)     * CC + n0 + nl];
            f.y = Wo[(size_t)(k0 + 2 * kp + 1) * CC + n0 + nl];
            __nv_bfloat162 hi, lo;
            bf16_split2(f, &hi, &lo);
            *(__nv_bfloat162*)&Bh[nl * KST + 2 * kp] = hi;
            *(__nv_bfloat162*)&Bl[nl * KST + 2 * kp] = lo;
        }
    };

    stage(0, 0);
    __syncthreads();
    const int NK = CC / 32;                          // 12
    for (int kc = 0; kc < NK; kc++) {
        int cur = kc & 1;
        uint32_t base = SB + cur * BUF_BYTES;
        MMA_TILE_LOOP_LDSM(d, base, base + ARR_BYTES, base + 2 * ARR_BYTES, base + 3 * ARR_BYTES)
        if (kc + 1 < NK) stage((kc + 1) * 32, cur ^ 1);
        __syncthreads();
    }

    #pragma unroll
    for (int mt = 0; mt < 4; mt++) {
        #pragma unroll
        for (int nt = 0; nt < 4; nt++) {
            int m = m0 + wm * 64 + mt * 16 + g;
            int c = n0 + wn * 32 + nt * 8 + 2 * t;
            float b0v = bo[c], b1v = bo[c + 1];
            if (m < MROWS2) {
                float2 o; o.x = d[mt][nt][0] + b0v; o.y = d[mt][nt][1] + b1v;
                *(float2*)&out[(size_t)m * CC + c] = o;
            }
            if (m + 8 < MROWS2) {
                float2 o; o.x = d[mt][nt][2] + b0v; o.y = d[mt][nt][3] + b1v;
                *(float2*)&out[(size_t)(m + 8) * CC + c] = o;
            }
        }
    }
}

// ------------------------------------------------------------------
extern "C" void kernel_launch(void* const* d_in, const int* in_sizes, int n_in,
                              void* d_out, int out_size) {
    const float* x   = (const float*)d_in[0];
    const float* Wq1 = (const float*)d_in[1];  const float* bq1 = (const float*)d_in[2];
    const float* Wq2 = (const float*)d_in[3];  const float* bq2 = (const float*)d_in[4];
    const float* Wk1 = (const float*)d_in[5];  const float* bk1 = (const float*)d_in[6];
    const float* Wk2 = (const float*)d_in[7];  const float* bk2 = (const float*)d_in[8];
    const float* Wv1 = (const float*)d_in[9];  const float* bv1 = (const float*)d_in[10];
    const float* Wv2 = (const float*)d_in[11]; const float* bv2 = (const float*)d_in[12];
    const float* Wo  = (const float*)d_in[13]; const float* bo  = (const float*)d_in[14];
    const float* wts = (const float*)d_in[15]; const float* gum = (const float*)d_in[16];
    float* out = (float*)d_out;

    cudaFuncSetAttribute(proj_kernel,   cudaFuncAttributeMaxDynamicSharedMemorySize, SMEM_TOTAL);
    cudaFuncSetAttribute(scores_kernel, cudaFuncAttributeMaxDynamicSharedMemorySize, SMEM_TOTAL);
    cudaFuncSetAttribute(av_kernel,     cudaFuncAttributeMaxDynamicSharedMemorySize, SMEM_TOTAL);
    cudaFuncSetAttribute(final_kernel,  cudaFuncAttributeMaxDynamicSharedMemorySize, SMEM_TOTAL);

    select_kernel<<<1, 1>>>(wts, gum);

    dim3 pg(CC / 128, (MROWS + 127) / 128, 4);              // 3 x 33 x 4
    proj_kernel<<<pg, 256, SMEM_TOTAL>>>(x, Wq1, bq1, Wq2, bq2, Wk1, bk1, Wk2, bk2,
                                         Wv1, bv1, Wv2, bv2);

    scores_kernel<<<dim3((N1 + 127) / 128, BHN), 256, SMEM_TOTAL>>>();  // 5 x 48

    softmax_kernel<<<(unsigned)(BHN * N1), 128>>>();

    av_kernel<<<dim3((N1 + 127) / 128, BHN), 256, SMEM_TOTAL>>>();      // 5 x 48

    final_kernel<<<dim3(CC / 128, (MROWS2 + 127) / 128, 1), 256, SMEM_TOTAL>>>(Wo, bo, out);
}

// round 16
// speedup vs baseline: 1.0914x; 1.0914x over previous
#include <cuda_runtime.h>
#include <cuda_bf16.h>
#include <stdint.h>
#include <math.h>

#define BB     8
#define M_TOT  1026
#define CC     384
#define N1     513
#define N1P    514          // padded (even) fp32 score row stride
#define SP     544          // bf16 exp'd score row stride (16B-aligned rows, zero pads)
#define HH     6
#define DD     64
#define BHN    (BB*HH)      // 48
#define MROWS  (BB*N1)      // 4104
#define MROWS2 (BB*M_TOT)   // 8208

// ---- scratch (device globals; no cudaMalloc allowed) ----
__device__ int   g_sel;
__device__ float g_Q [MROWS*CC];
__device__ float g_K [MROWS*CC];
__device__ float g_V1[MROWS*CC];
__device__ float g_V2[MROWS*CC];
__device__ float g_S [(size_t)BHN*N1*N1P];            // raw fp32 scores
__device__ __nv_bfloat16 g_Sh[(size_t)BHN*N1*SP + 256*SP];  // exp'd hi (slack rows)
__device__ __nv_bfloat16 g_Sl[(size_t)BHN*N1*SP + 256*SP];  // exp'd lo
__device__ __nv_bfloat16 g_Oh[(size_t)MROWS2*CC + 256*CC];  // AV out hi (slack)
__device__ __nv_bfloat16 g_Ol[(size_t)MROWS2*CC + 256*CC];  // AV out lo
__device__ float g_inv[BHN*N1];                       // 1/rowsum

// ------------------------------------------------------------------
// 0) straight-through gumbel selection: argmax(weights + noise)
// ------------------------------------------------------------------
__global__ void select_kernel(const float* __restrict__ w,
                              const float* __restrict__ g) {
    float best = w[0] + g[0];
    int bi = 0;
    #pragma unroll
    for (int i = 1; i < 4; i++) {
        float v = w[i] + g[i];
        if (v > best) { best = v; bi = i; }
    }
    g_sel = bi;
}

// ==================================================================
// bf16 3-pass (hi/lo split) tensor-core GEMM common pieces
// ==================================================================
#define KST  40         // bf16 row stride
#define KSTU 20         // u32 row stride
#define ARR_ELEMS  (128 * KST)          // 5120 bf16 per array
#define BUF_ELEMS  (4 * ARR_ELEMS)
#define ARR_BYTES  (ARR_ELEMS * 2)      // 10240
#define BUF_BYTES  (BUF_ELEMS * 2)      // 40960
#define SMEM_TOTAL (2 * BUF_BYTES)      // 81920

extern __shared__ __nv_bfloat16 dynsmem[];

__device__ __forceinline__ void bf16_split2(float2 f, __nv_bfloat162* hi, __nv_bfloat162* lo) {
    __nv_bfloat16 hx = __float2bfloat16(f.x);
    __nv_bfloat16 hy = __float2bfloat16(f.y);
    __nv_bfloat16 lx = __float2bfloat16(f.x - __bfloat162float(hx));
    __nv_bfloat16 ly = __float2bfloat16(f.y - __bfloat162float(hy));
    hi->x = hx; hi->y = hy;
    lo->x = lx; lo->y = ly;
}

__device__ __forceinline__ void mma_bf16(float* d, uint32_t a0, uint32_t a1,
                                         uint32_t a2, uint32_t a3,
                                         uint32_t b0, uint32_t b1) {
    asm volatile(
        "mma.sync.aligned.m16n8k16.row.col.f32.bf16.bf16.f32 "
        "{%0,%1,%2,%3},{%4,%5,%6,%7},{%8,%9},{%0,%1,%2,%3};"
        : "+f"(d[0]), "+f"(d[1]), "+f"(d[2]), "+f"(d[3])
        : "r"(a0), "r"(a1), "r"(a2), "r"(a3), "r"(b0), "r"(b1));
}

__device__ __forceinline__ void ldsm_x4(uint32_t& r0, uint32_t& r1,
                                        uint32_t& r2, uint32_t& r3, uint32_t a) {
    asm volatile("ldmatrix.sync.aligned.m8n8.x4.shared.b16 {%0,%1,%2,%3},[%4];"
                 : "=r"(r0), "=r"(r1), "=r"(r2), "=r"(r3) : "r"(a));
}

__device__ __forceinline__ void cp_async16(uint32_t dst, const void* src, int szbytes) {
    asm volatile("cp.async.cg.shared.global [%0], [%1], 16, %2;"
                 :: "r"(dst), "l"(src), "r"(szbytes));
}
#define CP_COMMIT() asm volatile("cp.async.commit_group;" ::: "memory")
#define CP_WAIT0()  asm volatile("cp.async.wait_group 0;" ::: "memory")

#define FRAG_SETUP()                                                   \
    const int warp = tid >> 5, lane = tid & 31;                        \
    const int wm = warp >> 2, wn = warp & 3;                           \
    const int g = lane >> 2, t = lane & 3;                             \
    const int lt = lane >> 3, lr = lane & 7;                           \
    const int aRow = (lt & 1) * 8 + lr;                                \
    const int aKw  = (lt >> 1) * 4;                                    \
    const int bRow = ((lt >> 1) ? 8 : 0) + lr;                         \
    const int bKw  = (lt & 1) * 4;                                     \
    (void)g; (void)t;

#define MMA_TILE_LOOP_LDSM(d, AhB, AlB, BhB, BlB)                                   \
    _Pragma("unroll")                                                               \
    for (int ks = 0; ks < 2; ks++) {                                                \
        const int ko = ks * 8;                                                      \
        uint32_t bh_[4][2], bl_[4][2];                                              \
        _Pragma("unroll")                                                           \
        for (int ntp = 0; ntp < 2; ntp++) {                                         \
            uint32_t off = (uint32_t)(((wn * 32 + ntp * 16 + bRow) * KSTU + ko + bKw) * 4); \
            ldsm_x4(bh_[2*ntp][0], bh_[2*ntp][1], bh_[2*ntp+1][0], bh_[2*ntp+1][1], (BhB) + off); \
            ldsm_x4(bl_[2*ntp][0], bl_[2*ntp][1], bl_[2*ntp+1][0], bl_[2*ntp+1][1], (BlB) + off); \
        }                                                                           \
        _Pragma("unroll")                                                           \
        for (int mt = 0; mt < 4; mt++) {                                            \
            uint32_t off = (uint32_t)(((wm * 64 + mt * 16 + aRow) * KSTU + ko + aKw) * 4);  \
            uint32_t ah0, ah1, ah2, ah3, al0, al1, al2, al3;                        \
            ldsm_x4(ah0, ah1, ah2, ah3, (AhB) + off);                               \
            ldsm_x4(al0, al1, al2, al3, (AlB) + off);                               \
            _Pragma("unroll")                                                       \
            for (int nt = 0; nt < 4; nt++) {                                        \
                mma_bf16(d[mt][nt], ah0, ah1, ah2, ah3, bh_[nt][0], bh_[nt][1]);    \
                mma_bf16(d[mt][nt], ah0, ah1, ah2, ah3, bl_[nt][0], bl_[nt][1]);    \
                mma_bf16(d[mt][nt], al0, al1, al2, al3, bh_[nt][0], bh_[nt][1]);    \
            }                                                                       \
        }                                                                           \
    }

#define ACC_DECL(d)                                                    \
    float d[4][4][4];                                                  \
    _Pragma("unroll")                                                  \
    for (int i = 0; i < 4; i++)                                        \
        _Pragma("unroll")                                              \
        for (int j = 0; j < 4; j++)                                    \
            _Pragma("unroll")                                          \
            for (int r = 0; r < 4; r++) d[i][j][r] = 0.f;

#define ACC_ZERO(d)                                                    \
    _Pragma("unroll")                                                  \
    for (int i = 0; i < 4; i++)                                        \
        _Pragma("unroll")                                              \
        for (int j = 0; j < 4; j++)                                    \
            _Pragma("unroll")                                          \
            for (int r = 0; r < 4; r++) d[i][j][r] = 0.f;

#define BUF_PTRS(buf)                                                  \
    __nv_bfloat16* Ah = dynsmem + (buf) * BUF_ELEMS;                   \
    __nv_bfloat16* Al = Ah + ARR_ELEMS;                                \
    __nv_bfloat16* Bh = Al + ARR_ELEMS;                                \
    __nv_bfloat16* Bl = Bh + ARR_ELEMS;

// ------------------------------------------------------------------
// 1) input projections via bf16 mma: 4 jobs, grid (3, 33, 4)  [R14]
// ------------------------------------------------------------------
__global__ __launch_bounds__(256, 2)
void proj_kernel(const float* __restrict__ x,
                 const float* Wq1, const float* bq1,
                 const float* Wq2, const float* bq2,
                 const float* Wk1, const float* bk1,
                 const float* Wk2, const float* bk2,
                 const float* Wv1, const float* bv1,
                 const float* Wv2, const float* bv2) {
    const int job = blockIdx.z;
    const int sel = g_sel;
    const float* W; const float* bias; float* OUT; int off;
    if (job == 0) { int qs = sel >> 1; W = qs ? Wq2 : Wq1; bias = qs ? bq2 : bq1; OUT = g_Q;  off = qs ? N1 : 0; }
    else if (job == 1) { int ks = sel & 1; W = ks ? Wk2 : Wk1; bias = ks ? bk2 : bk1; OUT = g_K;  off = ks ? N1 : 0; }
    else if (job == 2) { W = Wv1; bias = bv1; OUT = g_V1; off = 0;  }
    else               { W = Wv2; bias = bv2; OUT = g_V2; off = N1; }

    const int m0 = blockIdx.y * 128, n0 = blockIdx.x * 128;
    const int tid = threadIdx.x;
    FRAG_SETUP();
    ACC_DECL(d);
    const uint32_t SB = (uint32_t)__cvta_generic_to_shared(dynsmem);

    auto stage = [&](int k0, int buf) {
        BUF_PTRS(buf);
        #pragma unroll
        for (int it = 0; it < 8; it++) {
            int slot = tid + it * 256;
            int ml = slot >> 4, kp = slot & 15;
            int m = m0 + ml;
            float2 f = make_float2(0.f, 0.f);
            if (m < MROWS) {
                int b = m / N1, n = m % N1;
                f = *(const float2*)&x[((size_t)b * M_TOT + n + off) * CC + k0 + 2 * kp];
            }
            __nv_bfloat162 hi, lo;
            bf16_split2(f, &hi, &lo);
            *(__nv_bfloat162*)&Ah[ml * KST + 2 * kp] = hi;
            *(__nv_bfloat162*)&Al[ml * KST + 2 * kp] = lo;
        }
        #pragma unroll
        for (int it = 0; it < 8; it++) {
            int slot = tid + it * 256;
            int nl = slot & 127, kp = slot >> 7;
            float2 f;
            f.x = W[(size_t)(k0 + 2 * kp)     * CC + n0 + nl];
            f.y = W[(size_t)(k0 + 2 * kp + 1) * CC + n0 + nl];
            __nv_bfloat162 hi, lo;
            bf16_split2(f, &hi, &lo);
            *(__nv_bfloat162*)&Bh[nl * KST + 2 * kp] = hi;
            *(__nv_bfloat162*)&Bl[nl * KST + 2 * kp] = lo;
        }
    };

    stage(0, 0);
    __syncthreads();
    const int NK = CC / 32;                          // 12
    for (int kc = 0; kc < NK; kc++) {
        int cur = kc & 1;
        uint32_t base = SB + cur * BUF_BYTES;
        MMA_TILE_LOOP_LDSM(d, base, base + ARR_BYTES, base + 2 * ARR_BYTES, base + 3 * ARR_BYTES)
        if (kc + 1 < NK) stage((kc + 1) * 32, cur ^ 1);
        __syncthreads();
    }

    #pragma unroll
    for (int mt = 0; mt < 4; mt++) {
        #pragma unroll
        for (int nt = 0; nt < 4; nt++) {
            int m = m0 + wm * 64 + mt * 16 + g;
            int c = n0 + wn * 32 + nt * 8 + 2 * t;
            float b0v = bias[c], b1v = bias[c + 1];
            if (m < MROWS) {
                float2 o; o.x = d[mt][nt][0] + b0v; o.y = d[mt][nt][1] + b1v;
                *(float2*)&OUT[(size_t)m * CC + c] = o;
            }
            if (m + 8 < MROWS) {
                float2 o; o.x = d[mt][nt][2] + b0v; o.y = d[mt][nt][3] + b1v;
                *(float2*)&OUT[(size_t)(m + 8) * CC + c] = o;
            }
        }
    }
}

// ------------------------------------------------------------------
// 2) scores via bf16 mma, Q-resident: grid (5, 48)  [R14]
// ------------------------------------------------------------------
__global__ __launch_bounds__(256, 2)
void scores_kernel() {
    const int bh = blockIdx.y;
    const int b = bh / HH, hh = bh % HH;
    const int m0 = blockIdx.x * 128;

    const int tid = threadIdx.x;
    FRAG_SETUP();
    ACC_DECL(d);
    const uint32_t SB = (uint32_t)__cvta_generic_to_shared(dynsmem);

    #pragma unroll
    for (int c = 0; c < 2; c++) {
        __nv_bfloat16* Qh = dynsmem + (2 * c)     * ARR_ELEMS;
        __nv_bfloat16* Ql = dynsmem + (2 * c + 1) * ARR_ELEMS;
        #pragma unroll
        for (int it = 0; it < 8; it++) {
            int slot = tid + it * 256;
            int ml = slot >> 4, kp = slot & 15;
            int qi = m0 + ml;
            float2 f = make_float2(0.f, 0.f);
            if (qi < N1)
                f = *(const float2*)&g_Q[((size_t)b * N1 + qi) * CC + hh * DD + c * 32 + 2 * kp];
            __nv_bfloat162 hi, lo;
            bf16_split2(f, &hi, &lo);
            *(__nv_bfloat162*)&Qh[ml * KST + 2 * kp] = hi;
            *(__nv_bfloat162*)&Ql[ml * KST + 2 * kp] = lo;
        }
    }

    const float scale = 0.125f;  // 64^-0.5
    const size_t Sbase = (size_t)bh * N1 * N1P;

    for (int nt0 = 0; nt0 < 5; nt0++) {
        const int n0 = nt0 * 128;
        __syncthreads();
        #pragma unroll
        for (int c = 0; c < 2; c++) {
            __nv_bfloat16* Kh = dynsmem + (4 + 2 * c) * ARR_ELEMS;
            __nv_bfloat16* Kl = dynsmem + (5 + 2 * c) * ARR_ELEMS;
            #pragma unroll
            for (int it = 0; it < 8; it++) {
                int slot = tid + it * 256;
                int nl = slot >> 4, kp = slot & 15;
                int kj = n0 + nl;
                float2 f = make_float2(0.f, 0.f);
                if (kj < N1)
                    f = *(const float2*)&g_K[((size_t)b * N1 + kj) * CC + hh * DD + c * 32 + 2 * kp];
                __nv_bfloat162 hi, lo;
                bf16_split2(f, &hi, &lo);
                *(__nv_bfloat162*)&Kh[nl * KST + 2 * kp] = hi;
                *(__nv_bfloat162*)&Kl[nl * KST + 2 * kp] = lo;
            }
        }
        __syncthreads();

        ACC_ZERO(d);
        #pragma unroll
        for (int c = 0; c < 2; c++) {
            uint32_t qb = SB + (2 * c) * ARR_BYTES;
            uint32_t kb = SB + (4 + 2 * c) * ARR_BYTES;
            MMA_TILE_LOOP_LDSM(d, qb, qb + ARR_BYTES, kb, kb + ARR_BYTES)
        }

        #pragma unroll
        for (int mt = 0; mt < 4; mt++) {
            #pragma unroll
            for (int nt = 0; nt < 4; nt++) {
                int qi = m0 + wm * 64 + mt * 16 + g;
                int kj = n0 + wn * 32 + nt * 8 + 2 * t;
                if (qi < N1 && kj < N1) {
                    float2 o; o.x = d[mt][nt][0] * scale; o.y = d[mt][nt][1] * scale;
                    *(float2*)&g_S[Sbase + (size_t)qi * N1P + kj] = o;
                }
                if (qi + 8 < N1 && kj < N1) {
                    float2 o; o.x = d[mt][nt][2] * scale; o.y = d[mt][nt][3] * scale;
                    *(float2*)&g_S[Sbase + (size_t)(qi + 8) * N1P + kj] = o;
                }
            }
        }
    }
}

// ------------------------------------------------------------------
// 3) softmax: reads fp32 g_S vectorized, writes exp'd PRE-SPLIT to
//    g_Sh/g_Sl (stride SP, pads zeroed, paired u32 stores), 1/sum.
// ------------------------------------------------------------------
__global__ __launch_bounds__(128)
void softmax_kernel() {
    const size_t row = blockIdx.x;
    const float* p = g_S + row * N1P;
    __nv_bfloat16* ph = g_Sh + row * SP;
    __nv_bfloat16* pl = g_Sl + row * SP;
    const int t = threadIdx.x;
    __shared__ float redm[4];
    __shared__ float reds[4];

    // pairs: p0 = t (j=2t), p1 = t+128 (j=256+2t); element 512 by t==0
    float2 a = *(const float2*)&p[2 * t];
    float2 b = *(const float2*)&p[256 + 2 * t];
    float v512 = (t == 0) ? p[512] : -1e30f;

    float m = fmaxf(fmaxf(a.x, a.y), fmaxf(b.x, b.y));
    m = fmaxf(m, v512);
    #pragma unroll
    for (int o = 16; o > 0; o >>= 1) m = fmaxf(m, __shfl_xor_sync(0xffffffffu, m, o));
    if ((t & 31) == 0) redm[t >> 5] = m;
    __syncthreads();
    m = fmaxf(fmaxf(redm[0], redm[1]), fmaxf(redm[2], redm[3]));

    float s = 0.f;
    {
        float e0 = __expf(a.x - m), e1 = __expf(a.y - m);
        __nv_bfloat16 h0 = __float2bfloat16(e0), h1 = __float2bfloat16(e1);
        __nv_bfloat162 hp; hp.x = h0; hp.y = h1;
        __nv_bfloat162 lp;
        lp.x = __float2bfloat16(e0 - __bfloat162float(h0));
        lp.y = __float2bfloat16(e1 - __bfloat162float(h1));
        *(__nv_bfloat162*)&ph[2 * t] = hp;
        *(__nv_bfloat162*)&pl[2 * t] = lp;
        s += e0 + e1;
    }
    {
        float e0 = __expf(b.x - m), e1 = __expf(b.y - m);
        __nv_bfloat16 h0 = __float2bfloat16(e0), h1 = __float2bfloat16(e1);
        __nv_bfloat162 hp; hp.x = h0; hp.y = h1;
        __nv_bfloat162 lp;
        lp.x = __float2bfloat16(e0 - __bfloat162float(h0));
        lp.y = __float2bfloat16(e1 - __bfloat162float(h1));
        *(__nv_bfloat162*)&ph[256 + 2 * t] = hp;
        *(__nv_bfloat162*)&pl[256 + 2 * t] = lp;
        s += e0 + e1;
    }
    if (t == 0) {
        float e = __expf(v512 - m);
        __nv_bfloat16 h0 = __float2bfloat16(e);
        __nv_bfloat162 hp; hp.x = h0; hp.y = __float2bfloat16(0.f);
        __nv_bfloat162 lp;
        lp.x = __float2bfloat16(e - __bfloat162float(h0));
        lp.y = hp.y;
        *(__nv_bfloat162*)&ph[512] = hp;
        *(__nv_bfloat162*)&pl[512] = lp;
        s += e;
    } else if (t < 16) {
        __nv_bfloat162 z;
        z.x = __float2bfloat16(0.f); z.y = z.x;
        *(__nv_bfloat162*)&ph[512 + 2 * t] = z;   // pads 514..543
        *(__nv_bfloat162*)&pl[512 + 2 * t] = z;
    }
    #pragma unroll
    for (int o = 16; o > 0; o >>= 1) s += __shfl_xor_sync(0xffffffffu, s, o);
    if ((t & 31) == 0) reds[t >> 5] = s;
    __syncthreads();
    if (t == 0) g_inv[row] = 1.f / (reds[0] + reds[1] + reds[2] + reds[3]);
}

// ------------------------------------------------------------------
// 4) AV via bf16 mma: grid (5, 48); K-dim 544.
//    A staging = cp.async 16B from pre-split g_Sh/g_Sl (zero-fill OOB);
//    B (V) staging = fp32 register split (R14 form).
//    Epilogue writes pre-split g_Oh/g_Ol.
// ------------------------------------------------------------------
__global__ __launch_bounds__(256, 2)
void av_kernel() {
    const int bh = blockIdx.y;
    const int b = bh / HH, hh = bh % HH;
    const int m0 = blockIdx.x * 128;

    const int tid = threadIdx.x;
    FRAG_SETUP();
    ACC_DECL(d);
    const uint32_t SB = (uint32_t)__cvta_generic_to_shared(dynsmem);
    const size_t Sbase = (size_t)bh * N1 * SP;

    auto stageA = [&](int k0, int buf) {
        uint32_t dAh = SB + buf * BUF_BYTES;
        #pragma unroll
        for (int it = 0; it < 2; it++) {
            int slot = tid + it * 256;           // 0..511
            int row = slot >> 2, seg = slot & 3;
            int qi = m0 + row;
            int sz = (qi < N1) ? 16 : 0;
            size_t so = Sbase + (size_t)qi * SP + k0 + seg * 8;
            uint32_t doff = (uint32_t)((row * KST + seg * 8) * 2);
            cp_async16(dAh + doff, g_Sh + so, sz);
            cp_async16(dAh + ARR_BYTES + doff, g_Sl + so, sz);
        }
    };
    auto stageB = [&](int k0, int buf) {
        BUF_PTRS(buf);
        #pragma unroll
        for (int it = 0; it < 8; it++) {
            int slot = tid + it * 256;
            int nl = slot & 127, kp = slot >> 7;
            int ki = k0 + 2 * kp;
            int col = hh * DD + (nl & 63);
            const float* V = (nl < 64) ? g_V1 : g_V2;
            float2 f = make_float2(0.f, 0.f);
            if (ki     < N1) f.x = V[((size_t)b * N1 + ki)     * CC + col];
            if (ki + 1 < N1) f.y = V[((size_t)b * N1 + ki + 1) * CC + col];
            __nv_bfloat162 hi, lo;
            bf16_split2(f, &hi, &lo);
            *(__nv_bfloat162*)&Bh[nl * KST + 2 * kp] = hi;
            *(__nv_bfloat162*)&Bl[nl * KST + 2 * kp] = lo;
        }
    };

    stageA(0, 0);
    stageB(0, 0);
    CP_COMMIT();
    CP_WAIT0();
    __syncthreads();

    const int NK = 17;                               // 544 / 32
    for (int kc = 0; kc < NK; kc++) {
        int cur = kc & 1;
        if (kc + 1 < NK) stageA((kc + 1) * 32, cur ^ 1);   // async, hides under MMA
        uint32_t base = SB + cur * BUF_BYTES;
        MMA_TILE_LOOP_LDSM(d, base, base + ARR_BYTES, base + 2 * ARR_BYTES, base + 3 * ARR_BYTES)
        if (kc + 1 < NK) { stageB((kc + 1) * 32, cur ^ 1); CP_COMMIT(); }
        CP_WAIT0();
        __syncthreads();
    }

    #pragma unroll
    for (int mt = 0; mt < 4; mt++) {
        #pragma unroll
        for (int nt = 0; nt < 4; nt++) {
            int qi = m0 + wm * 64 + mt * 16 + g;
            int c = wn * 32 + nt * 8 + 2 * t;                 // 0..126
            int row_off = (c < 64) ? 0 : N1;
            int ci = hh * DD + (c & 63);
            if (qi < N1) {
                float sc = g_inv[bh * N1 + qi];
                float2 o; o.x = d[mt][nt][0] * sc; o.y = d[mt][nt][1] * sc;
                __nv_bfloat162 hi, lo;
                bf16_split2(o, &hi, &lo);
                size_t base = ((size_t)b * M_TOT + row_off + qi) * CC + ci;
                *(__nv_bfloat162*)&g_Oh[base] = hi;
                *(__nv_bfloat162*)&g_Ol[base] = lo;
            }
            if (qi + 8 < N1) {
                float sc = g_inv[bh * N1 + qi + 8];
                float2 o; o.x = d[mt][nt][2] * sc; o.y = d[mt][nt][3] * sc;
                __nv_bfloat162 hi, lo;
                bf16_split2(o, &hi, &lo);
                size_t base = ((size_t)b * M_TOT + row_off + qi + 8) * CC + ci;
                *(__nv_bfloat162*)&g_Oh[base] = hi;
                *(__nv_bfloat162*)&g_Ol[base] = lo;
            }
        }
    }
}

// ------------------------------------------------------------------
// 5) output projection via bf16 mma: grid (3, 65)
//    A staging = cp.async from pre-split g_Oh/g_Ol
// ------------------------------------------------------------------
__global__ __launch_bounds__(256, 2)
void final_kernel(const float* __restrict__ Wo,
                  const float* __restrict__ bo,
                  float* __restrict__ out) {
    const int m0 = blockIdx.y * 128, n0 = blockIdx.x * 128;
    const int tid = threadIdx.x;
    FRAG_SETUP();
    ACC_DECL(d);
    const uint32_t SB = (uint32_t)__cvta_generic_to_shared(dynsmem);

    auto stageA = [&](int k0, int buf) {
        uint32_t dAh = SB + buf * BUF_BYTES;
        #pragma unroll
        for (int it = 0; it < 2; it++) {
            int slot = tid + it * 256;
            int row = slot >> 2, seg = slot & 3;
            int m = m0 + row;
            int sz = (m < MROWS2) ? 16 : 0;
            size_t so = (size_t)m * CC + k0 + seg * 8;
            uint32_t doff = (uint32_t)((row * KST + seg * 8) * 2);
            cp_async16(dAh + doff, g_Oh + so, sz);
            cp_async16(dAh + ARR_BYTES + doff, g_Ol + so, sz);
        }
    };
    auto stageB = [&](int k0, int buf) {
        BUF_PTRS(buf);
        #pragma unroll
        for (int it = 0; it < 8; it++) {
            int slot = tid + it * 256;
            int nl = slot & 127, kp = slot >> 7;
            float2 f;
            f.x = Wo[(size_t)(k0 + 2 * kp)     * CC + n0 + nl];
            f.y = Wo[(size_t)(k0 + 2 * kp + 1) * CC + n0 + nl];
            __nv_bfloat162 hi, lo;
            bf16_split2(f, &hi, &lo);
            *(__nv_bfloat162*)&Bh[nl * KST + 2 * kp] = hi;
            *(__nv_bfloat162*)&Bl[nl * KST + 2 * kp] = lo;
        }
    };

    stageA(0, 0);
    stageB(0, 0);
    CP_COMMIT();
    CP_WAIT0();
    __syncthreads();

    const int NK = CC / 32;                          // 12
    for (int kc = 0; kc < NK; kc++) {
        int cur = kc & 1;
        if (kc + 1 < NK) stageA((kc + 1) * 32, cur ^ 1);
        uint32_t base = SB + cur * BUF_BYTES;
        MMA_TILE_LOOP_LDSM(d, base, base + ARR_BYTES, base + 2 * ARR_BYTES, base + 3 * ARR_BYTES)
        if (kc + 1 < NK) { stageB((kc + 1) * 32, cur ^ 1); CP_COMMIT(); }
        CP_WAIT0();
        __syncthreads();
    }

    #pragma unroll
    for (int mt = 0; mt < 4; mt++) {
        #pragma unroll
        for (int nt = 0; nt < 4; nt++) {
            int m = m0 + wm * 64 + mt * 16 + g;
            int c = n0 + wn * 32 + nt * 8 + 2 * t;
            float b0v = bo[c], b1v = bo[c + 1];
            if (m < MROWS2) {
                float2 o; o.x = d[mt][nt][0] + b0v; o.y = d[mt][nt][1] + b1v;
                *(float2*)&out[(size_t)m * CC + c] = o;
            }
            if (m + 8 < MROWS2) {
                float2 o; o.x = d[mt][nt][2] + b0v; o.y = d[mt][nt][3] + b1v;
                *(float2*)&out[(size_t)(m + 8) * CC + c] = o;
            }
        }
    }
}

// ------------------------------------------------------------------
extern "C" void kernel_launch(void* const* d_in, const int* in_sizes, int n_in,
                              void* d_out, int out_size) {
    const float* x   = (const float*)d_in[0];
    const float* Wq1 = (const float*)d_in[1];  const float* bq1 = (const float*)d_in[2];
    const float* Wq2 = (const float*)d_in[3];  const float* bq2 = (const float*)d_in[4];
    const float* Wk1 = (const float*)d_in[5];  const float* bk1 = (const float*)d_in[6];
    const float* Wk2 = (const float*)d_in[7];  const float* bk2 = (const float*)d_in[8];
    const float* Wv1 = (const float*)d_in[9];  const float* bv1 = (const float*)d_in[10];
    const float* Wv2 = (const float*)d_in[11]; const float* bv2 = (const float*)d_in[12];
    const float* Wo  = (const float*)d_in[13]; const float* bo  = (const float*)d_in[14];
    const float* wts = (const float*)d_in[15]; const float* gum = (const float*)d_in[16];
    float* out = (float*)d_out;

    cudaFuncSetAttribute(proj_kernel,   cudaFuncAttributeMaxDynamicSharedMemorySize, SMEM_TOTAL);
    cudaFuncSetAttribute(scores_kernel, cudaFuncAttributeMaxDynamicSharedMemorySize, SMEM_TOTAL);
    cudaFuncSetAttribute(av_kernel,     cudaFuncAttributeMaxDynamicSharedMemorySize, SMEM_TOTAL);
    cudaFuncSetAttribute(final_kernel,  cudaFuncAttributeMaxDynamicSharedMemorySize, SMEM_TOTAL);

    select_kernel<<<1, 1>>>(wts, gum);

    dim3 pg(CC / 128, (MROWS + 127) / 128, 4);              // 3 x 33 x 4
    proj_kernel<<<pg, 256, SMEM_TOTAL>>>(x, Wq1, bq1, Wq2, bq2, Wk1, bk1, Wk2, bk2,
                                         Wv1, bv1, Wv2, bv2);

    scores_kernel<<<dim3((N1 + 127) / 128, BHN), 256, SMEM_TOTAL>>>();  // 5 x 48

    softmax_kernel<<<(unsigned)(BHN * N1), 128>>>();

    av_kernel<<<dim3((N1 + 127) / 128, BHN), 256, SMEM_TOTAL>>>();      // 5 x 48

    final_kernel<<<dim3(CC / 128, (MROWS2 + 127) / 128, 1), 256, SMEM_TOTAL>>>(Wo, bo, out);
}